// round 2
// baseline (speedup 1.0000x reference)
#include <cuda_runtime.h>

#define BB 16
#define NN 4096
#define SS 1024
#define KK 32
#define DD 64
#define ROWS (BB*SS*KK)        // 524288
#define XYZ_OUT (BB*SS*3)      // 49152
#define INV_ROWS (1.0f/524288.0f)

// ---------------- scratch (static device globals; no allocation) ----------------
__device__ float g_x0[(size_t)ROWS*64];    // layer0 pre-BN activations
__device__ float g_x1[(size_t)ROWS*64];    // layer1 pre-BN activations
__device__ float g_x2[(size_t)ROWS*128];   // layer2 pre-BN activations
__device__ int   g_knn[ROWS];              // 32 NN indices per query
__device__ float g_newxyz[BB*SS*3];
__device__ float g_stats[512];             // L0: sum[0:64) sq[64:128); L1: +128; L2: sum[256:384) sq[384:512)
__device__ float g_sb[512];                // per-layer folded BN scale/bias

// ---------------- zero stats ----------------
__global__ void zero_stats_kernel(float* stats) {
    if (threadIdx.x < 512) stats[threadIdx.x] = 0.0f;
}

// ---------------- KNN: 32 smallest distances per query ----------------
// grid (16, 8), block 256. smem caches batch xyz (SoA + squared norms).
// Each warp holds the resident 32-smallest set, one (dist,idx) per lane.
__global__ void knn_kernel(const float* __restrict__ xyz, const int* __restrict__ fps,
                           int* __restrict__ knn, float* __restrict__ newxyz,
                           float* __restrict__ out)
{
    extern __shared__ float sm[];
    float* px = sm; float* py = sm + NN; float* pz = sm + 2*NN; float* pp = sm + 3*NN;
    int b = blockIdx.x;
    const float* xb = xyz + (size_t)b*NN*3;
    for (int i = threadIdx.x; i < NN; i += blockDim.x) {
        float x = xb[3*i], y = xb[3*i+1], z = xb[3*i+2];
        px[i] = x; py[i] = y; pz[i] = z; pp[i] = x*x + y*y + z*z;
    }
    __syncthreads();
    int warp = threadIdx.x >> 5, lane = threadIdx.x & 31;

    for (int qi = 0; qi < 16; ++qi) {
        int s = blockIdx.y*128 + warp*16 + qi;
        int n0 = fps[b*SS + s];
        float qx = px[n0], qy = py[n0], qz = pz[n0], qq = pp[n0];

        // init resident set with points 0..31
        float d; int myi;
        {
            int i = lane;
            d = fmaf(-2.0f, fmaf(qx, px[i], fmaf(qy, py[i], qz*pz[i])), qq) + pp[i];
            myi = i;
        }
        float thr; int amax;
        {
            float v = d; int l = lane;
            #pragma unroll
            for (int off = 16; off; off >>= 1) {
                float ov = __shfl_down_sync(0xffffffffu, v, off);
                int   ol = __shfl_down_sync(0xffffffffu, l, off);
                if (ov > v) { v = ov; l = ol; }
            }
            thr  = __shfl_sync(0xffffffffu, v, 0);
            amax = __shfl_sync(0xffffffffu, l, 0);
        }

        for (int base = 32; base < NN; base += 32) {
            int i = base + lane;
            float dc = fmaf(-2.0f, fmaf(qx, px[i], fmaf(qy, py[i], qz*pz[i])), qq) + pp[i];
            unsigned m = __ballot_sync(0xffffffffu, dc < thr);
            while (m) {
                int src = __ffs(m) - 1; m &= m - 1;
                float dcand = __shfl_sync(0xffffffffu, dc, src);
                if (dcand < thr) {       // recheck vs updated threshold
                    if (lane == amax) { d = dcand; myi = base + src; }
                    float v = d; int l = lane;
                    #pragma unroll
                    for (int off = 16; off; off >>= 1) {
                        float ov = __shfl_down_sync(0xffffffffu, v, off);
                        int   ol = __shfl_down_sync(0xffffffffu, l, off);
                        if (ov > v) { v = ov; l = ol; }
                    }
                    thr  = __shfl_sync(0xffffffffu, v, 0);
                    amax = __shfl_sync(0xffffffffu, l, 0);
                }
            }
        }
        knn[((size_t)b*SS + s)*KK + lane] = myi;
        if (lane == 0) {
            size_t o = ((size_t)b*SS + s)*3;
            newxyz[o] = qx; newxyz[o+1] = qy; newxyz[o+2] = qz;
            out[o] = qx; out[o+1] = qy; out[o+2] = qz;
        }
    }
}

// ---------------- Layer 0: gather + concat + 67->64 linear + stats ----------------
// block 256, tile 128 rows. smem: inT[128*69], Wt[67*64] (c-major), stats.
__global__ __launch_bounds__(256) void layer0_kernel(
    const float* __restrict__ xyz, const float* __restrict__ points,
    const int* __restrict__ knn, const float* __restrict__ newxyz,
    const float* __restrict__ W, const float* __restrict__ bconv,
    float* __restrict__ xout, float* __restrict__ statS, float* __restrict__ statQ)
{
    extern __shared__ float sm[];
    float* inT = sm;                 // 128 * 69
    float* Wt  = sm + 128*69;        // 67 * 64  (Wt[c*64 + o])
    float* sS  = Wt + 67*64;
    float* sQ  = sS + 64;
    int t = threadIdx.x;
    size_t rowBase = (size_t)blockIdx.x * 128;

    for (int e = t; e < 67*64; e += 256) {
        int o = e / 67, c = e - o*67;
        Wt[c*64 + o] = W[e];
    }
    if (t < 64) { sS[t] = 0.0f; sQ[t] = 0.0f; }

    // gather input rows: 2 threads per row
    {
        int r = t >> 1, half = t & 1;
        size_t row = rowBase + r;
        int b = (int)(row >> 15);
        int s = (int)((row >> 5) & 1023);
        int n = knn[row];
        const float4* prow = (const float4*)(points + ((size_t)b*NN + n)*DD);
        float* dst = inT + r*69;
        if (half == 0) {
            size_t xo = ((size_t)b*NN + n)*3;
            size_t qo = ((size_t)b*SS + s)*3;
            dst[0] = xyz[xo]   - newxyz[qo];
            dst[1] = xyz[xo+1] - newxyz[qo+1];
            dst[2] = xyz[xo+2] - newxyz[qo+2];
            #pragma unroll
            for (int j = 0; j < 8; ++j) {
                float4 v = prow[j];
                dst[3+4*j] = v.x; dst[4+4*j] = v.y; dst[5+4*j] = v.z; dst[6+4*j] = v.w;
            }
        } else {
            #pragma unroll
            for (int j = 8; j < 16; ++j) {
                float4 v = prow[j];
                dst[3+4*j] = v.x; dst[4+4*j] = v.y; dst[5+4*j] = v.z; dst[6+4*j] = v.w;
            }
        }
    }
    __syncthreads();

    int oc = t & 7, rc = t >> 3;         // 8 out-groups of 8, 32 row-groups of 4
    float acc[4][8];
    #pragma unroll
    for (int i = 0; i < 4; ++i)
        #pragma unroll
        for (int j = 0; j < 8; ++j) acc[i][j] = bconv[oc*8 + j];

    const float* ip = inT + rc*4*69;
    #pragma unroll 2
    for (int c = 0; c < 67; ++c) {
        float a0 = ip[c], a1 = ip[69+c], a2 = ip[138+c], a3 = ip[207+c];
        const float* wc = Wt + c*64 + oc*8;
        float4 w0v = *(const float4*)(wc);
        float4 w1v = *(const float4*)(wc + 4);
        float wv[8] = {w0v.x, w0v.y, w0v.z, w0v.w, w1v.x, w1v.y, w1v.z, w1v.w};
        #pragma unroll
        for (int j = 0; j < 8; ++j) {
            acc[0][j] = fmaf(a0, wv[j], acc[0][j]);
            acc[1][j] = fmaf(a1, wv[j], acc[1][j]);
            acc[2][j] = fmaf(a2, wv[j], acc[2][j]);
            acc[3][j] = fmaf(a3, wv[j], acc[3][j]);
        }
    }

    #pragma unroll
    for (int i = 0; i < 4; ++i) {
        float* orow = xout + (rowBase + rc*4 + i)*64 + oc*8;
        ((float4*)orow)[0] = make_float4(acc[i][0], acc[i][1], acc[i][2], acc[i][3]);
        ((float4*)orow)[1] = make_float4(acc[i][4], acc[i][5], acc[i][6], acc[i][7]);
    }
    #pragma unroll
    for (int j = 0; j < 8; ++j) {
        float s = acc[0][j] + acc[1][j] + acc[2][j] + acc[3][j];
        float q = acc[0][j]*acc[0][j] + acc[1][j]*acc[1][j] + acc[2][j]*acc[2][j] + acc[3][j]*acc[3][j];
        atomicAdd(&sS[oc*8 + j], s);
        atomicAdd(&sQ[oc*8 + j], q);
    }
    __syncthreads();
    if (t < 64) { atomicAdd(&statS[t], sS[t]); atomicAdd(&statQ[t], sQ[t]); }
}

// ---------------- Layers 1/2: BN(prev)+ReLU fused on load, 64->COUT linear + stats ----------------
template<int COUT, int OT>
__global__ __launch_bounds__(256) void layer12_kernel(
    const float* __restrict__ xin, float* __restrict__ xout,
    const float* __restrict__ W, const float* __restrict__ bconv,
    const float* __restrict__ sbin,   // scale[0:64), bias[64:128)
    float* __restrict__ statS, float* __restrict__ statQ)
{
    extern __shared__ float sm[];
    float* inT = sm;                   // 128 * 69
    float* Wt  = sm + 128*69;          // 64 * COUT (Wt[c*COUT + o])
    float* sS  = Wt + 64*COUT;
    float* sQ  = sS + COUT;
    float* sci = sQ + COUT;            // 128: scale+bias for input channels
    int t = threadIdx.x;
    size_t rowBase = (size_t)blockIdx.x * 128;

    if (t < 128) sci[t] = sbin[t];
    for (int e = t; e < COUT*64; e += 256) {
        int o = e >> 6, c = e & 63;
        Wt[c*COUT + o] = W[e];
    }
    for (int e = t; e < COUT; e += 256) { sS[e] = 0.0f; sQ[e] = 0.0f; }
    __syncthreads();

    // load + BN + ReLU into smem
    const float4* src = (const float4*)(xin + rowBase*64);
    #pragma unroll
    for (int k = 0; k < 8; ++k) {
        int e4 = t + k*256;
        float4 v = src[e4];
        int lin = e4*4; int r = lin >> 6; int c = lin & 63;
        inT[r*69 + c + 0] = fmaxf(fmaf(v.x, sci[c+0], sci[64+c+0]), 0.0f);
        inT[r*69 + c + 1] = fmaxf(fmaf(v.y, sci[c+1], sci[64+c+1]), 0.0f);
        inT[r*69 + c + 2] = fmaxf(fmaf(v.z, sci[c+2], sci[64+c+2]), 0.0f);
        inT[r*69 + c + 3] = fmaxf(fmaf(v.w, sci[c+3], sci[64+c+3]), 0.0f);
    }
    __syncthreads();

    int oc = t & 7, rc = t >> 3;
    float acc[4][OT];
    #pragma unroll
    for (int i = 0; i < 4; ++i)
        #pragma unroll
        for (int j = 0; j < OT; ++j) acc[i][j] = bconv[oc*OT + j];

    const float* ip = inT + rc*4*69;
    #pragma unroll 2
    for (int c = 0; c < 64; ++c) {
        float a0 = ip[c], a1 = ip[69+c], a2 = ip[138+c], a3 = ip[207+c];
        const float* wc = Wt + c*COUT + oc*OT;
        #pragma unroll
        for (int j4 = 0; j4 < OT/4; ++j4) {
            float4 wv = *(const float4*)(wc + 4*j4);
            acc[0][4*j4+0] = fmaf(a0, wv.x, acc[0][4*j4+0]);
            acc[0][4*j4+1] = fmaf(a0, wv.y, acc[0][4*j4+1]);
            acc[0][4*j4+2] = fmaf(a0, wv.z, acc[0][4*j4+2]);
            acc[0][4*j4+3] = fmaf(a0, wv.w, acc[0][4*j4+3]);
            acc[1][4*j4+0] = fmaf(a1, wv.x, acc[1][4*j4+0]);
            acc[1][4*j4+1] = fmaf(a1, wv.y, acc[1][4*j4+1]);
            acc[1][4*j4+2] = fmaf(a1, wv.z, acc[1][4*j4+2]);
            acc[1][4*j4+3] = fmaf(a1, wv.w, acc[1][4*j4+3]);
            acc[2][4*j4+0] = fmaf(a2, wv.x, acc[2][4*j4+0]);
            acc[2][4*j4+1] = fmaf(a2, wv.y, acc[2][4*j4+1]);
            acc[2][4*j4+2] = fmaf(a2, wv.z, acc[2][4*j4+2]);
            acc[2][4*j4+3] = fmaf(a2, wv.w, acc[2][4*j4+3]);
            acc[3][4*j4+0] = fmaf(a3, wv.x, acc[3][4*j4+0]);
            acc[3][4*j4+1] = fmaf(a3, wv.y, acc[3][4*j4+1]);
            acc[3][4*j4+2] = fmaf(a3, wv.z, acc[3][4*j4+2]);
            acc[3][4*j4+3] = fmaf(a3, wv.w, acc[3][4*j4+3]);
        }
    }

    #pragma unroll
    for (int i = 0; i < 4; ++i) {
        float* orow = xout + (rowBase + rc*4 + i)*COUT + oc*OT;
        #pragma unroll
        for (int j4 = 0; j4 < OT/4; ++j4)
            ((float4*)orow)[j4] = make_float4(acc[i][4*j4], acc[i][4*j4+1], acc[i][4*j4+2], acc[i][4*j4+3]);
    }
    #pragma unroll
    for (int j = 0; j < OT; ++j) {
        float s = acc[0][j] + acc[1][j] + acc[2][j] + acc[3][j];
        float q = acc[0][j]*acc[0][j] + acc[1][j]*acc[1][j] + acc[2][j]*acc[2][j] + acc[3][j]*acc[3][j];
        atomicAdd(&sS[oc*OT + j], s);
        atomicAdd(&sQ[oc*OT + j], q);
    }
    __syncthreads();
    if (t < COUT) { atomicAdd(&statS[t], sS[t]); atomicAdd(&statQ[t], sQ[t]); }
}

// ---------------- finalize BN params ----------------
__global__ void finalize_kernel(const float* __restrict__ gamma, const float* __restrict__ beta,
                                float* __restrict__ stats, float* __restrict__ sb, int cnt)
{
    int c = threadIdx.x;
    if (c < cnt) {
        float mean = stats[c] * INV_ROWS;
        float var  = stats[cnt + c] * INV_ROWS - mean*mean;
        float sc   = gamma[c] * rsqrtf(var + 1e-5f);
        sb[c]       = sc;
        sb[cnt + c] = beta[c] - mean*sc;
    }
}

// ---------------- max over K with BN+ReLU of layer2 ----------------
__global__ void max_kernel(const float* __restrict__ x2, const float* __restrict__ sb,
                           float* __restrict__ out)
{
    int bs = blockIdx.x, ch = threadIdx.x;
    float sc = sb[ch], bi = sb[128 + ch];
    const float* p = x2 + (size_t)bs*KK*128 + ch;
    float m = 0.0f;   // ReLU lower bound; subsumes relu in the max
    #pragma unroll
    for (int k = 0; k < KK; ++k) m = fmaxf(m, fmaf(p[k*128], sc, bi));
    out[XYZ_OUT + (size_t)bs*128 + ch] = m;
}

// ---------------- launch ----------------
extern "C" void kernel_launch(void* const* d_in, const int* in_sizes, int n_in,
                              void* d_out, int out_size)
{
    const float* xyz    = (const float*)d_in[0];
    const float* points = (const float*)d_in[1];
    const int*   fps    = (const int*)d_in[2];
    const float* w0  = (const float*)d_in[3];
    const float* b0  = (const float*)d_in[4];
    const float* g0  = (const float*)d_in[5];
    const float* be0 = (const float*)d_in[6];
    const float* w1  = (const float*)d_in[7];
    const float* b1  = (const float*)d_in[8];
    const float* g1  = (const float*)d_in[9];
    const float* be1 = (const float*)d_in[10];
    const float* w2  = (const float*)d_in[11];
    const float* b2  = (const float*)d_in[12];
    const float* g2  = (const float*)d_in[13];
    const float* be2 = (const float*)d_in[14];
    float* out = (float*)d_out;

    float *px0, *px1, *px2, *pnx, *pst, *psb;
    int* pknn;
    cudaGetSymbolAddress((void**)&px0,  g_x0);
    cudaGetSymbolAddress((void**)&px1,  g_x1);
    cudaGetSymbolAddress((void**)&px2,  g_x2);
    cudaGetSymbolAddress((void**)&pnx,  g_newxyz);
    cudaGetSymbolAddress((void**)&pst,  g_stats);
    cudaGetSymbolAddress((void**)&psb,  g_sb);
    cudaGetSymbolAddress((void**)&pknn, g_knn);

    const int SM_KNN = 4*NN*4;                                      // 65536
    const int SM0 = 128*69*4 + 67*64*4 + 2*64*4;                    // 52992
    const int SM1 = 128*69*4 + 64*64*4 + 2*64*4 + 128*4;            // 52736
    const int SM2 = 128*69*4 + 64*128*4 + 2*128*4 + 128*4;          // 69632

    cudaFuncSetAttribute(knn_kernel, cudaFuncAttributeMaxDynamicSharedMemorySize, SM_KNN);
    cudaFuncSetAttribute(layer0_kernel, cudaFuncAttributeMaxDynamicSharedMemorySize, SM0);
    cudaFuncSetAttribute(layer12_kernel<64,8>,  cudaFuncAttributeMaxDynamicSharedMemorySize, SM1);
    cudaFuncSetAttribute(layer12_kernel<128,16>, cudaFuncAttributeMaxDynamicSharedMemorySize, SM2);

    zero_stats_kernel<<<1, 512>>>(pst);
    knn_kernel<<<dim3(BB, 8), 256, SM_KNN>>>(xyz, fps, pknn, pnx, out);
    layer0_kernel<<<ROWS/128, 256, SM0>>>(xyz, points, pknn, pnx, w0, b0, px0, pst, pst + 64);
    finalize_kernel<<<1, 64>>>(g0, be0, pst, psb, 64);
    layer12_kernel<64,8><<<ROWS/128, 256, SM1>>>(px0, px1, w1, b1, psb, pst + 128, pst + 192);
    finalize_kernel<<<1, 64>>>(g1, be1, pst + 128, psb + 128, 64);
    layer12_kernel<128,16><<<ROWS/128, 256, SM2>>>(px1, px2, w2, b2, psb + 128, pst + 256, pst + 384);
    finalize_kernel<<<1, 128>>>(g2, be2, pst + 256, psb + 256, 128);
    max_kernel<<<BB*SS, 128>>>(px2, psb + 256, out);
}

// round 3
// speedup vs baseline: 2.6060x; 2.6060x over previous
#include <cuda_runtime.h>
#include <cstdint>

#define BB 16
#define NN 4096
#define SS 1024
#define KK 32
#define DD 64
#define ROWS (BB*SS*KK)        // 524288
#define XYZ_OUT (BB*SS*3)      // 49152
#define INV_ROWS (1.0f/524288.0f)

// ---------------- scratch ----------------
__device__ float g_x0[(size_t)ROWS*64];
__device__ float g_x1[(size_t)ROWS*64];
__device__ float g_x2[(size_t)ROWS*128];
__device__ int   g_knn[ROWS];
__device__ float g_newxyz[BB*SS*3];
__device__ float g_stats[512];
__device__ float g_sb[512];

__global__ void zero_stats_kernel(float* stats) {
    if (threadIdx.x < 512) stats[threadIdx.x] = 0.0f;
}

// ---------------- tf32 helpers ----------------
__device__ __forceinline__ uint32_t f2tf(float x) {
    uint32_t r; asm("cvt.rna.tf32.f32 %0, %1;" : "=r"(r) : "f"(x)); return r;
}
__device__ __forceinline__ void mma_tf32(float& d0, float& d1, float& d2, float& d3,
    uint32_t a0, uint32_t a1, uint32_t a2, uint32_t a3, uint32_t b0, uint32_t b1)
{
    asm volatile("mma.sync.aligned.m16n8k8.row.col.f32.tf32.tf32.f32 "
        "{%0,%1,%2,%3},{%4,%5,%6,%7},{%8,%9},{%0,%1,%2,%3};"
        : "+f"(d0), "+f"(d1), "+f"(d2), "+f"(d3)
        : "r"(a0), "r"(a1), "r"(a2), "r"(a3), "r"(b0), "r"(b1));
}

// ---------------- KNN ----------------
// grid (16, 16), block 256 (8 warps, 8 queries/warp). smem caches batch xyz SoA.
__global__ void knn_kernel(const float* __restrict__ xyz, const int* __restrict__ fps,
                           int* __restrict__ knn, float* __restrict__ newxyz,
                           float* __restrict__ out)
{
    extern __shared__ float sm[];
    float* px = sm; float* py = sm + NN; float* pz = sm + 2*NN; float* pp = sm + 3*NN;
    int b = blockIdx.x;
    const float* xb = xyz + (size_t)b*NN*3;
    for (int i = threadIdx.x; i < NN; i += blockDim.x) {
        float x = xb[3*i], y = xb[3*i+1], z = xb[3*i+2];
        px[i] = x; py[i] = y; pz[i] = z; pp[i] = x*x + y*y + z*z;
    }
    __syncthreads();
    int warp = threadIdx.x >> 5, lane = threadIdx.x & 31;

    for (int qi = 0; qi < 8; ++qi) {
        int s = blockIdx.y*64 + warp*8 + qi;
        int n0 = fps[b*SS + s];
        float qx = px[n0], qy = py[n0], qz = pz[n0], qq = pp[n0];

        float d; int myi;
        {
            int i = lane;
            d = fmaf(-2.0f, fmaf(qx, px[i], fmaf(qy, py[i], qz*pz[i])), qq) + pp[i];
            myi = i;
        }
        float thr; int amax;
        {
            float v = d; int l = lane;
            #pragma unroll
            for (int off = 16; off; off >>= 1) {
                float ov = __shfl_down_sync(0xffffffffu, v, off);
                int   ol = __shfl_down_sync(0xffffffffu, l, off);
                if (ov > v) { v = ov; l = ol; }
            }
            thr  = __shfl_sync(0xffffffffu, v, 0);
            amax = __shfl_sync(0xffffffffu, l, 0);
        }

        for (int base = 32; base < NN; base += 32) {
            int i = base + lane;
            float dc = fmaf(-2.0f, fmaf(qx, px[i], fmaf(qy, py[i], qz*pz[i])), qq) + pp[i];
            unsigned m = __ballot_sync(0xffffffffu, dc < thr);
            while (m) {
                int src = __ffs(m) - 1; m &= m - 1;
                float dcand = __shfl_sync(0xffffffffu, dc, src);
                if (dcand < thr) {
                    if (lane == amax) { d = dcand; myi = base + src; }
                    float v = d; int l = lane;
                    #pragma unroll
                    for (int off = 16; off; off >>= 1) {
                        float ov = __shfl_down_sync(0xffffffffu, v, off);
                        int   ol = __shfl_down_sync(0xffffffffu, l, off);
                        if (ov > v) { v = ov; l = ol; }
                    }
                    thr  = __shfl_sync(0xffffffffu, v, 0);
                    amax = __shfl_sync(0xffffffffu, l, 0);
                }
            }
        }
        knn[((size_t)b*SS + s)*KK + lane] = myi;
        if (lane == 0) {
            size_t o = ((size_t)b*SS + s)*3;
            newxyz[o] = qx; newxyz[o+1] = qy; newxyz[o+2] = qz;
            out[o] = qx; out[o+1] = qy; out[o+2] = qz;
        }
    }
}

// ---------------- shared MMA compute (3xTF32) ----------------
// sHi/sLo: [128][STRIDE] activation tiles (tf32-rounded hi, residual lo).
// Weights = A operand (16 out-channels per m-tile), resident in regs hi/lo.
template<int COUT, int K_REAL, int NK, int STRIDE>
__device__ __forceinline__ void mma_compute(
    const float* __restrict__ sHi, const float* __restrict__ sLo,
    const float* __restrict__ W, const float* __restrict__ bconv,
    float* __restrict__ xout, size_t rowBase, float* sS, float* sQ)
{
    constexpr int M_TILES = COUT/16;
    constexpr int HALVES  = 8/M_TILES;
    constexpr int ROWS_PW = 128/HALVES;
    constexpr int NG      = ROWS_PW/8;
    int warp = threadIdx.x >> 5, lane = threadIdx.x & 31;
    int g = lane >> 2, t = lane & 3;
    int mb = (warp % M_TILES) * 16;
    int rowOff = (warp / M_TILES) * ROWS_PW;

    uint32_t ahi[NK][4], alo[NK][4];
    #pragma unroll
    for (int ks = 0; ks < NK; ++ks) {
        #pragma unroll
        for (int j = 0; j < 4; ++j) {
            int r = mb + g + (j & 1) * 8;
            int c = ks*8 + t + (j >> 1) * 4;
            float v = (c < K_REAL) ? W[r*K_REAL + c] : 0.0f;
            uint32_t h = f2tf(v);
            ahi[ks][j] = h;
            alo[ks][j] = f2tf(v - __uint_as_float(h));
        }
    }
    float bias0 = bconv[mb + g], bias1 = bconv[mb + 8 + g];
    float s0 = 0, q0 = 0, s1 = 0, q1 = 0;

    #pragma unroll 1
    for (int ng = 0; ng < NG; ++ng) {
        int nb = rowOff + ng*8;
        float d0 = bias0, d1 = bias0, d2 = bias1, d3 = bias1;
        const float* bh = sHi + (nb + g)*STRIDE + t;
        const float* bl = sLo + (nb + g)*STRIDE + t;
        #pragma unroll
        for (int ks = 0; ks < NK; ++ks) {
            uint32_t b0h = __float_as_uint(bh[ks*8]);
            uint32_t b1h = __float_as_uint(bh[ks*8 + 4]);
            uint32_t b0l = __float_as_uint(bl[ks*8]);
            uint32_t b1l = __float_as_uint(bl[ks*8 + 4]);
            mma_tf32(d0,d1,d2,d3, ahi[ks][0],ahi[ks][1],ahi[ks][2],ahi[ks][3], b0h,b1h);
            mma_tf32(d0,d1,d2,d3, ahi[ks][0],ahi[ks][1],ahi[ks][2],ahi[ks][3], b0l,b1l);
            mma_tf32(d0,d1,d2,d3, alo[ks][0],alo[ks][1],alo[ks][2],alo[ks][3], b0h,b1h);
        }
        // D[m][n]: m = channel, n = activation row.  c0:(g, 2t) c1:(g, 2t+1) c2:(g+8, 2t) c3:(g+8, 2t+1)
        float* p = xout + (rowBase + nb + 2*t)*COUT + mb + g;
        p[0] = d0; p[COUT] = d1; p[8] = d2; p[COUT + 8] = d3;
        s0 += d0 + d1; q0 += d0*d0 + d1*d1;
        s1 += d2 + d3; q1 += d2*d2 + d3*d3;
    }
    #pragma unroll
    for (int off = 1; off < 4; off <<= 1) {
        s0 += __shfl_xor_sync(0xffffffffu, s0, off);
        q0 += __shfl_xor_sync(0xffffffffu, q0, off);
        s1 += __shfl_xor_sync(0xffffffffu, s1, off);
        q1 += __shfl_xor_sync(0xffffffffu, q1, off);
    }
    if (t == 0) {
        atomicAdd(&sS[mb + g], s0);     atomicAdd(&sQ[mb + g], q0);
        atomicAdd(&sS[mb + 8 + g], s1); atomicAdd(&sQ[mb + 8 + g], q1);
    }
}

// ---------------- Layer 0: gather + concat + 67->64, tensor cores ----------------
__global__ __launch_bounds__(256) void layer0_mma(
    const float* __restrict__ xyz, const float* __restrict__ points,
    const int* __restrict__ knn, const float* __restrict__ newxyz,
    const float* __restrict__ W, const float* __restrict__ bconv,
    float* __restrict__ xout, float* __restrict__ statS, float* __restrict__ statQ)
{
    extern __shared__ float sm[];
    float* sHi = sm;                // 128*76
    float* sLo = sm + 128*76;
    float* sS  = sLo + 128*76;      // 64
    float* sQ  = sS + 64;
    int tid = threadIdx.x;
    size_t rowBase = (size_t)blockIdx.x * 128;
    if (tid < 64) { sS[tid] = 0.0f; sQ[tid] = 0.0f; }

    {
        int r = tid >> 1, half = tid & 1;
        size_t row = rowBase + r;
        int b = (int)(row >> 15);
        int s = (int)((row >> 5) & 1023);
        int n = knn[row];
        const float4* prow = (const float4*)(points + ((size_t)b*NN + n)*DD);
        float* dh = sHi + r*76; float* dl = sLo + r*76;
        auto put = [&](int c, float v) {
            uint32_t h = f2tf(v);
            dh[c] = __uint_as_float(h);
            dl[c] = __uint_as_float(f2tf(v - __uint_as_float(h)));
        };
        if (half == 0) {
            size_t xo = ((size_t)b*NN + n)*3;
            size_t qo = ((size_t)b*SS + s)*3;
            put(0, xyz[xo]   - newxyz[qo]);
            put(1, xyz[xo+1] - newxyz[qo+1]);
            put(2, xyz[xo+2] - newxyz[qo+2]);
            #pragma unroll
            for (int j = 0; j < 8; ++j) {
                float4 v = prow[j];
                put(3+4*j, v.x); put(4+4*j, v.y); put(5+4*j, v.z); put(6+4*j, v.w);
            }
        } else {
            #pragma unroll
            for (int j = 8; j < 16; ++j) {
                float4 v = prow[j];
                put(3+4*j, v.x); put(4+4*j, v.y); put(5+4*j, v.z); put(6+4*j, v.w);
            }
            #pragma unroll
            for (int c = 67; c < 72; ++c) { dh[c] = 0.0f; dl[c] = 0.0f; }
        }
    }
    __syncthreads();
    mma_compute<64, 67, 9, 76>(sHi, sLo, W, bconv, xout, rowBase, sS, sQ);
    __syncthreads();
    if (tid < 64) { atomicAdd(&statS[tid], sS[tid]); atomicAdd(&statQ[tid], sQ[tid]); }
}

// ---------------- Layers 1/2: BN+ReLU fused on load, tensor cores ----------------
template<int COUT>
__global__ __launch_bounds__(256) void layer12_mma(
    const float* __restrict__ xin, float* __restrict__ xout,
    const float* __restrict__ W, const float* __restrict__ bconv,
    const float* __restrict__ sbin,
    float* __restrict__ statS, float* __restrict__ statQ)
{
    extern __shared__ float sm[];
    float* sHi = sm;                // 128*68
    float* sLo = sm + 128*68;
    float* sS  = sLo + 128*68;      // COUT
    float* sQ  = sS + COUT;
    float* sci = sQ + COUT;         // 128
    int tid = threadIdx.x;
    size_t rowBase = (size_t)blockIdx.x * 128;

    if (tid < 128) sci[tid] = sbin[tid];
    for (int e = tid; e < COUT; e += 256) { sS[e] = 0.0f; sQ[e] = 0.0f; }
    __syncthreads();

    const float4* src = (const float4*)(xin + rowBase*64);
    #pragma unroll
    for (int k = 0; k < 8; ++k) {
        int e4 = tid + k*256;
        float4 v = src[e4];
        int lin = e4*4; int r = lin >> 6; int c = lin & 63;
        float* dh = sHi + r*68 + c; float* dl = sLo + r*68 + c;
        float ys[4] = {
            fmaxf(fmaf(v.x, sci[c+0], sci[64+c+0]), 0.0f),
            fmaxf(fmaf(v.y, sci[c+1], sci[64+c+1]), 0.0f),
            fmaxf(fmaf(v.z, sci[c+2], sci[64+c+2]), 0.0f),
            fmaxf(fmaf(v.w, sci[c+3], sci[64+c+3]), 0.0f) };
        #pragma unroll
        for (int i = 0; i < 4; ++i) {
            uint32_t h = f2tf(ys[i]);
            dh[i] = __uint_as_float(h);
            dl[i] = __uint_as_float(f2tf(ys[i] - __uint_as_float(h)));
        }
    }
    __syncthreads();
    mma_compute<COUT, 64, 8, 68>(sHi, sLo, W, bconv, xout, rowBase, sS, sQ);
    __syncthreads();
    if (tid < COUT) { atomicAdd(&statS[tid], sS[tid]); atomicAdd(&statQ[tid], sQ[tid]); }
}

// ---------------- finalize BN params ----------------
__global__ void finalize_kernel(const float* __restrict__ gamma, const float* __restrict__ beta,
                                float* __restrict__ stats, float* __restrict__ sb, int cnt)
{
    int c = threadIdx.x;
    if (c < cnt) {
        float mean = stats[c] * INV_ROWS;
        float var  = stats[cnt + c] * INV_ROWS - mean*mean;
        float sc   = gamma[c] * rsqrtf(var + 1e-5f);
        sb[c]       = sc;
        sb[cnt + c] = beta[c] - mean*sc;
    }
}

// ---------------- max over K with BN+ReLU of layer2 ----------------
__global__ void max_kernel(const float* __restrict__ x2, const float* __restrict__ sb,
                           float* __restrict__ out)
{
    int bs = blockIdx.x, ch = threadIdx.x;
    float sc = sb[ch], bi = sb[128 + ch];
    const float* p = x2 + (size_t)bs*KK*128 + ch;
    float m = 0.0f;
    #pragma unroll
    for (int k = 0; k < KK; ++k) m = fmaxf(m, fmaf(p[k*128], sc, bi));
    out[XYZ_OUT + (size_t)bs*128 + ch] = m;
}

// ---------------- launch ----------------
extern "C" void kernel_launch(void* const* d_in, const int* in_sizes, int n_in,
                              void* d_out, int out_size)
{
    const float* xyz    = (const float*)d_in[0];
    const float* points = (const float*)d_in[1];
    const int*   fps    = (const int*)d_in[2];
    const float* w0  = (const float*)d_in[3];
    const float* b0  = (const float*)d_in[4];
    const float* g0  = (const float*)d_in[5];
    const float* be0 = (const float*)d_in[6];
    const float* w1  = (const float*)d_in[7];
    const float* b1  = (const float*)d_in[8];
    const float* g1  = (const float*)d_in[9];
    const float* be1 = (const float*)d_in[10];
    const float* w2  = (const float*)d_in[11];
    const float* b2  = (const float*)d_in[12];
    const float* g2  = (const float*)d_in[13];
    const float* be2 = (const float*)d_in[14];
    float* out = (float*)d_out;

    float *px0, *px1, *px2, *pnx, *pst, *psb;
    int* pknn;
    cudaGetSymbolAddress((void**)&px0,  g_x0);
    cudaGetSymbolAddress((void**)&px1,  g_x1);
    cudaGetSymbolAddress((void**)&px2,  g_x2);
    cudaGetSymbolAddress((void**)&pnx,  g_newxyz);
    cudaGetSymbolAddress((void**)&pst,  g_stats);
    cudaGetSymbolAddress((void**)&psb,  g_sb);
    cudaGetSymbolAddress((void**)&pknn, g_knn);

    const int SM_KNN = 4*NN*4;                                  // 65536
    const int SM0 = (128*76*2 + 2*64)*4;                        // 78336
    const int SM1 = (128*68*2 + 2*64 + 128)*4;                  // 70656
    const int SM2 = (128*68*2 + 2*128 + 128)*4;                 // 71168

    cudaFuncSetAttribute(knn_kernel, cudaFuncAttributeMaxDynamicSharedMemorySize, SM_KNN);
    cudaFuncSetAttribute(layer0_mma, cudaFuncAttributeMaxDynamicSharedMemorySize, SM0);
    cudaFuncSetAttribute(layer12_mma<64>,  cudaFuncAttributeMaxDynamicSharedMemorySize, SM1);
    cudaFuncSetAttribute(layer12_mma<128>, cudaFuncAttributeMaxDynamicSharedMemorySize, SM2);

    zero_stats_kernel<<<1, 512>>>(pst);
    knn_kernel<<<dim3(BB, 16), 256, SM_KNN>>>(xyz, fps, pknn, pnx, out);
    layer0_mma<<<ROWS/128, 256, SM0>>>(xyz, points, pknn, pnx, w0, b0, px0, pst, pst + 64);
    finalize_kernel<<<1, 64>>>(g0, be0, pst, psb, 64);
    layer12_mma<64><<<ROWS/128, 256, SM1>>>(px0, px1, w1, b1, psb, pst + 128, pst + 192);
    finalize_kernel<<<1, 64>>>(g1, be1, pst + 128, psb + 128, 64);
    layer12_mma<128><<<ROWS/128, 256, SM2>>>(px1, px2, w2, b2, psb + 128, pst + 256, pst + 384);
    finalize_kernel<<<1, 128>>>(g2, be2, pst + 256, psb + 256, 128);
    max_kernel<<<BB*SS, 128>>>(px2, psb + 256, out);
}

// round 4
// speedup vs baseline: 3.3857x; 1.2992x over previous
#include <cuda_runtime.h>
#include <cuda_bf16.h>
#include <cstdint>

#define BB 16
#define NN 4096
#define SS 1024
#define KK 32
#define DD 64
#define ROWS (BB*SS*KK)        // 524288
#define XYZ_OUT (BB*SS*3)      // 49152
#define INV_ROWS (1.0f/524288.0f)

// ---------------- scratch ----------------
__device__ float g_x0[(size_t)ROWS*64];
__device__ float g_x1[(size_t)ROWS*64];
__device__ float g_maxv[(size_t)BB*SS*128];
__device__ float g_minv[(size_t)BB*SS*128];
__device__ int   g_knn[ROWS];
__device__ float g_newxyz[BB*SS*3];
__device__ float g_stats[512];
__device__ float g_sb[512];

__global__ void zero_stats_kernel(float* stats) {
    if (threadIdx.x < 512) stats[threadIdx.x] = 0.0f;
}

// ---------------- bf16 helpers ----------------
__device__ __forceinline__ void split2(float v0, float v1, uint32_t& hi, uint32_t& lo) {
    __nv_bfloat16 h0 = __float2bfloat16(v0), h1 = __float2bfloat16(v1);
    __nv_bfloat16 l0 = __float2bfloat16(v0 - __bfloat162float(h0));
    __nv_bfloat16 l1 = __float2bfloat16(v1 - __bfloat162float(h1));
    hi = (uint32_t)__bfloat16_as_ushort(h0) | ((uint32_t)__bfloat16_as_ushort(h1) << 16);
    lo = (uint32_t)__bfloat16_as_ushort(l0) | ((uint32_t)__bfloat16_as_ushort(l1) << 16);
}
__device__ __forceinline__ void mma_bf16(float& d0, float& d1, float& d2, float& d3,
    uint32_t a0, uint32_t a1, uint32_t a2, uint32_t a3, uint32_t b0, uint32_t b1)
{
    asm volatile("mma.sync.aligned.m16n8k16.row.col.f32.bf16.bf16.f32 "
        "{%0,%1,%2,%3},{%4,%5,%6,%7},{%8,%9},{%0,%1,%2,%3};"
        : "+f"(d0), "+f"(d1), "+f"(d2), "+f"(d3)
        : "r"(a0), "r"(a1), "r"(a2), "r"(a3), "r"(b0), "r"(b1));
}

// ---------------- KNN ----------------
// grid (16, 16), block 256 (8 warps, 8 queries/warp). smem caches batch xyz as float4 (x,y,z,|p|^2).
__global__ void knn_kernel(const float* __restrict__ xyz, const int* __restrict__ fps,
                           int* __restrict__ knn, float* __restrict__ newxyz,
                           float* __restrict__ out)
{
    extern __shared__ float4 sm4[];
    int b = blockIdx.x;
    const float* xb = xyz + (size_t)b*NN*3;
    for (int i = threadIdx.x; i < NN; i += blockDim.x) {
        float x = xb[3*i], y = xb[3*i+1], z = xb[3*i+2];
        sm4[i] = make_float4(x, y, z, x*x + y*y + z*z);
    }
    __syncthreads();
    int warp = threadIdx.x >> 5, lane = threadIdx.x & 31;

    for (int qi = 0; qi < 8; ++qi) {
        int s = blockIdx.y*64 + warp*8 + qi;
        int n0 = fps[b*SS + s];
        float4 q = sm4[n0];
        float qx = q.x, qy = q.y, qz = q.z, qq = q.w;

        float d; int myi;
        {
            float4 p = sm4[lane];
            d = fmaf(-2.0f, fmaf(qx, p.x, fmaf(qy, p.y, qz*p.z)), qq) + p.w;
            myi = lane;
        }
        float thr; int amax;
        {
            float v = d; int l = lane;
            #pragma unroll
            for (int off = 16; off; off >>= 1) {
                float ov = __shfl_down_sync(0xffffffffu, v, off);
                int   ol = __shfl_down_sync(0xffffffffu, l, off);
                if (ov > v) { v = ov; l = ol; }
            }
            thr  = __shfl_sync(0xffffffffu, v, 0);
            amax = __shfl_sync(0xffffffffu, l, 0);
        }

        for (int base = 32; base < NN; base += 32) {
            int i = base + lane;
            float4 p = sm4[i];
            float dc = fmaf(-2.0f, fmaf(qx, p.x, fmaf(qy, p.y, qz*p.z)), qq) + p.w;
            unsigned m = __ballot_sync(0xffffffffu, dc < thr);
            while (m) {
                int src = __ffs(m) - 1; m &= m - 1;
                float dcand = __shfl_sync(0xffffffffu, dc, src);
                if (dcand < thr) {
                    if (lane == amax) { d = dcand; myi = base + src; }
                    float v = d; int l = lane;
                    #pragma unroll
                    for (int off = 16; off; off >>= 1) {
                        float ov = __shfl_down_sync(0xffffffffu, v, off);
                        int   ol = __shfl_down_sync(0xffffffffu, l, off);
                        if (ov > v) { v = ov; l = ol; }
                    }
                    thr  = __shfl_sync(0xffffffffu, v, 0);
                    amax = __shfl_sync(0xffffffffu, l, 0);
                }
            }
        }
        knn[((size_t)b*SS + s)*KK + lane] = myi;
        if (lane == 0) {
            size_t o = ((size_t)b*SS + s)*3;
            newxyz[o] = qx; newxyz[o+1] = qy; newxyz[o+2] = qz;
            out[o] = qx; out[o+1] = qy; out[o+2] = qz;
        }
    }
}

// ---------------- shared MMA compute (bf16x3, m16n8k16) ----------------
// sHi/sLo: [128][STRIDE u32] activation tiles (packed bf16 pairs: hi, residual lo).
// Weights = A operand; D rows = out-channels, D cols = activation rows.
template<int COUT, int K_REAL, int NK, int STRIDE, bool MAXMIN>
__device__ __forceinline__ void mma_compute_bf16(
    const uint32_t* __restrict__ sHi, const uint32_t* __restrict__ sLo,
    const float* __restrict__ W, const float* __restrict__ bconv,
    float* __restrict__ xout, size_t rowBase, float* sS, float* sQ,
    float* __restrict__ gmax, float* __restrict__ gmin)
{
    constexpr int M_TILES = COUT/16;
    constexpr int HALVES  = 8/M_TILES;
    constexpr int ROWS_PW = 128/HALVES;
    constexpr int NG      = ROWS_PW/8;
    int warp = threadIdx.x >> 5, lane = threadIdx.x & 31;
    int g = lane >> 2, t = lane & 3;
    int mb = (warp % M_TILES) * 16;
    int rowOff = (warp / M_TILES) * ROWS_PW;

    uint32_t ahi[NK][4], alo[NK][4];
    #pragma unroll
    for (int ks = 0; ks < NK; ++ks) {
        #pragma unroll
        for (int j = 0; j < 4; ++j) {
            int r = mb + g + (j & 1) * 8;
            int c0 = ks*16 + 2*t + (j >> 1) * 8;
            float v0 = (c0     < K_REAL) ? W[r*K_REAL + c0]     : 0.0f;
            float v1 = (c0 + 1 < K_REAL) ? W[r*K_REAL + c0 + 1] : 0.0f;
            split2(v0, v1, ahi[ks][j], alo[ks][j]);
        }
    }
    float bias0 = bconv[mb + g], bias1 = bconv[mb + 8 + g];
    float s0 = 0, q0 = 0, s1 = 0, q1 = 0;
    float mx0 = -3.4e38f, mx1 = -3.4e38f, mn0 = 3.4e38f, mn1 = 3.4e38f;

    #pragma unroll 1
    for (int ng = 0; ng < NG; ++ng) {
        int nb = rowOff + ng*8;
        float d0 = bias0, d1 = bias0, d2 = bias1, d3 = bias1;
        const uint32_t* bh = sHi + (nb + g)*STRIDE + t;
        const uint32_t* bl = sLo + (nb + g)*STRIDE + t;
        #pragma unroll
        for (int ks = 0; ks < NK; ++ks) {
            uint32_t b0h = bh[ks*8];
            uint32_t b1h = bh[ks*8 + 4];
            uint32_t b0l = bl[ks*8];
            uint32_t b1l = bl[ks*8 + 4];
            mma_bf16(d0,d1,d2,d3, ahi[ks][0],ahi[ks][1],ahi[ks][2],ahi[ks][3], b0h,b1h);
            mma_bf16(d0,d1,d2,d3, ahi[ks][0],ahi[ks][1],ahi[ks][2],ahi[ks][3], b0l,b1l);
            mma_bf16(d0,d1,d2,d3, alo[ks][0],alo[ks][1],alo[ks][2],alo[ks][3], b0h,b1h);
        }
        if constexpr (!MAXMIN) {
            float* p = xout + (rowBase + nb + 2*t)*COUT + mb + g;
            p[0] = d0; p[COUT] = d1; p[8] = d2; p[COUT + 8] = d3;
        }
        s0 += d0 + d1; q0 += d0*d0 + d1*d1;
        s1 += d2 + d3; q1 += d2*d2 + d3*d3;
        if constexpr (MAXMIN) {
            mx0 = fmaxf(mx0, fmaxf(d0, d1)); mn0 = fminf(mn0, fminf(d0, d1));
            mx1 = fmaxf(mx1, fmaxf(d2, d3)); mn1 = fminf(mn1, fminf(d2, d3));
            if ((ng & 3) == 3) {
                #pragma unroll
                for (int off = 1; off < 4; off <<= 1) {
                    mx0 = fmaxf(mx0, __shfl_xor_sync(0xffffffffu, mx0, off));
                    mn0 = fminf(mn0, __shfl_xor_sync(0xffffffffu, mn0, off));
                    mx1 = fmaxf(mx1, __shfl_xor_sync(0xffffffffu, mx1, off));
                    mn1 = fminf(mn1, __shfl_xor_sync(0xffffffffu, mn1, off));
                }
                if (t == 0) {
                    int bs = (int)(rowBase >> 5) + (ng >> 2);
                    gmax[bs*128 + mb + g]     = mx0;  gmin[bs*128 + mb + g]     = mn0;
                    gmax[bs*128 + mb + 8 + g] = mx1;  gmin[bs*128 + mb + 8 + g] = mn1;
                }
                mx0 = mx1 = -3.4e38f; mn0 = mn1 = 3.4e38f;
            }
        }
    }
    #pragma unroll
    for (int off = 1; off < 4; off <<= 1) {
        s0 += __shfl_xor_sync(0xffffffffu, s0, off);
        q0 += __shfl_xor_sync(0xffffffffu, q0, off);
        s1 += __shfl_xor_sync(0xffffffffu, s1, off);
        q1 += __shfl_xor_sync(0xffffffffu, q1, off);
    }
    if (t == 0) {
        atomicAdd(&sS[mb + g], s0);     atomicAdd(&sQ[mb + g], q0);
        atomicAdd(&sS[mb + 8 + g], s1); atomicAdd(&sQ[mb + 8 + g], q1);
    }
}

// ---------------- Layer 0: gather + concat + 67->64 (padded 80) ----------------
// smem: sHi/sLo bf16 [128][88] (stride 44 u32), stats.
__global__ __launch_bounds__(256) void layer0_mma(
    const float* __restrict__ xyz, const float* __restrict__ points,
    const int* __restrict__ knn, const float* __restrict__ newxyz,
    const float* __restrict__ W, const float* __restrict__ bconv,
    float* __restrict__ xout, float* __restrict__ statS, float* __restrict__ statQ)
{
    extern __shared__ char smraw[];
    __nv_bfloat16* sHi = (__nv_bfloat16*)smraw;         // 128*88
    __nv_bfloat16* sLo = sHi + 128*88;
    float* sS = (float*)(sLo + 128*88);
    float* sQ = sS + 64;
    int tid = threadIdx.x;
    size_t rowBase = (size_t)blockIdx.x * 128;
    if (tid < 64) { sS[tid] = 0.0f; sQ[tid] = 0.0f; }

    {
        int r = tid >> 1, half = tid & 1;
        size_t row = rowBase + r;
        int b = (int)(row >> 15);
        int s = (int)((row >> 5) & 1023);
        int n = knn[row];
        const float4* prow = (const float4*)(points + ((size_t)b*NN + n)*DD);
        __nv_bfloat16* dh = sHi + r*88;
        __nv_bfloat16* dl = sLo + r*88;
        auto put = [&](int c, float v) {
            __nv_bfloat16 h = __float2bfloat16(v);
            dh[c] = h;
            dl[c] = __float2bfloat16(v - __bfloat162float(h));
        };
        if (half == 0) {
            size_t xo = ((size_t)b*NN + n)*3;
            size_t qo = ((size_t)b*SS + s)*3;
            put(0, xyz[xo]   - newxyz[qo]);
            put(1, xyz[xo+1] - newxyz[qo+1]);
            put(2, xyz[xo+2] - newxyz[qo+2]);
            #pragma unroll
            for (int j = 0; j < 8; ++j) {
                float4 v = prow[j];
                put(3+4*j, v.x); put(4+4*j, v.y); put(5+4*j, v.z); put(6+4*j, v.w);
            }
        } else {
            #pragma unroll
            for (int j = 8; j < 16; ++j) {
                float4 v = prow[j];
                put(3+4*j, v.x); put(4+4*j, v.y); put(5+4*j, v.z); put(6+4*j, v.w);
            }
            #pragma unroll
            for (int c = 67; c < 80; ++c) {
                dh[c] = __ushort_as_bfloat16(0); dl[c] = __ushort_as_bfloat16(0);
            }
        }
    }
    __syncthreads();
    mma_compute_bf16<64, 67, 5, 44, false>((const uint32_t*)sHi, (const uint32_t*)sLo,
        W, bconv, xout, rowBase, sS, sQ, nullptr, nullptr);
    __syncthreads();
    if (tid < 64) { atomicAdd(&statS[tid], sS[tid]); atomicAdd(&statQ[tid], sQ[tid]); }
}

// ---------------- Layers 1/2: BN+ReLU fused on load ----------------
template<int COUT, bool MAXMIN>
__global__ __launch_bounds__(256) void layer12_mma(
    const float* __restrict__ xin, float* __restrict__ xout,
    const float* __restrict__ W, const float* __restrict__ bconv,
    const float* __restrict__ sbin,
    float* __restrict__ statS, float* __restrict__ statQ,
    float* __restrict__ gmax, float* __restrict__ gmin)
{
    extern __shared__ char smraw[];
    uint32_t* sHi = (uint32_t*)smraw;       // 128*36
    uint32_t* sLo = sHi + 128*36;
    float* sS  = (float*)(sLo + 128*36);    // COUT
    float* sQ  = sS + COUT;
    float* sci = sQ + COUT;                 // 128
    int tid = threadIdx.x;
    size_t rowBase = (size_t)blockIdx.x * 128;

    if (tid < 128) sci[tid] = sbin[tid];
    for (int e = tid; e < COUT; e += 256) { sS[e] = 0.0f; sQ[e] = 0.0f; }
    __syncthreads();

    const float4* src = (const float4*)(xin + rowBase*64);
    #pragma unroll
    for (int k = 0; k < 8; ++k) {
        int e4 = tid + k*256;
        float4 v = src[e4];
        int lin = e4*4; int r = lin >> 6; int c = lin & 63;
        float y0 = fmaxf(fmaf(v.x, sci[c+0], sci[64+c+0]), 0.0f);
        float y1 = fmaxf(fmaf(v.y, sci[c+1], sci[64+c+1]), 0.0f);
        float y2 = fmaxf(fmaf(v.z, sci[c+2], sci[64+c+2]), 0.0f);
        float y3 = fmaxf(fmaf(v.w, sci[c+3], sci[64+c+3]), 0.0f);
        uint2 hv, lv;
        split2(y0, y1, hv.x, lv.x);
        split2(y2, y3, hv.y, lv.y);
        int off = r*36 + (c >> 1);
        *(uint2*)(sHi + off) = hv;
        *(uint2*)(sLo + off) = lv;
    }
    __syncthreads();
    mma_compute_bf16<COUT, 64, 4, 36, MAXMIN>(sHi, sLo, W, bconv, xout, rowBase,
        sS, sQ, gmax, gmin);
    __syncthreads();
    if (tid < COUT) { atomicAdd(&statS[tid], sS[tid]); atomicAdd(&statQ[tid], sQ[tid]); }
}

// ---------------- finalize BN params ----------------
__global__ void finalize_kernel(const float* __restrict__ gamma, const float* __restrict__ beta,
                                float* __restrict__ stats, float* __restrict__ sb, int cnt)
{
    int c = threadIdx.x;
    if (c < cnt) {
        float mean = stats[c] * INV_ROWS;
        float var  = stats[cnt + c] * INV_ROWS - mean*mean;
        float sc   = gamma[c] * rsqrtf(var + 1e-5f);
        sb[c]       = sc;
        sb[cnt + c] = beta[c] - mean*sc;
    }
}

// ---------------- final: BN+ReLU applied to max/min over K ----------------
__global__ void final_max_kernel(const float* __restrict__ gmax, const float* __restrict__ gmin,
                                 const float* __restrict__ sb, float* __restrict__ out)
{
    int i = blockIdx.x*256 + threadIdx.x;
    int ch = i & 127;
    float sc = sb[ch], bi = sb[128 + ch];
    float v = (sc >= 0.0f) ? gmax[i] : gmin[i];
    out[XYZ_OUT + i] = fmaxf(fmaf(v, sc, bi), 0.0f);
}

// ---------------- launch ----------------
extern "C" void kernel_launch(void* const* d_in, const int* in_sizes, int n_in,
                              void* d_out, int out_size)
{
    const float* xyz    = (const float*)d_in[0];
    const float* points = (const float*)d_in[1];
    const int*   fps    = (const int*)d_in[2];
    const float* w0  = (const float*)d_in[3];
    const float* b0  = (const float*)d_in[4];
    const float* g0  = (const float*)d_in[5];
    const float* be0 = (const float*)d_in[6];
    const float* w1  = (const float*)d_in[7];
    const float* b1  = (const float*)d_in[8];
    const float* g1  = (const float*)d_in[9];
    const float* be1 = (const float*)d_in[10];
    const float* w2  = (const float*)d_in[11];
    const float* b2  = (const float*)d_in[12];
    const float* g2  = (const float*)d_in[13];
    const float* be2 = (const float*)d_in[14];
    float* out = (float*)d_out;

    float *px0, *px1, *pmx, *pmn, *pnx, *pst, *psb;
    int* pknn;
    cudaGetSymbolAddress((void**)&px0,  g_x0);
    cudaGetSymbolAddress((void**)&px1,  g_x1);
    cudaGetSymbolAddress((void**)&pmx,  g_maxv);
    cudaGetSymbolAddress((void**)&pmn,  g_minv);
    cudaGetSymbolAddress((void**)&pnx,  g_newxyz);
    cudaGetSymbolAddress((void**)&pst,  g_stats);
    cudaGetSymbolAddress((void**)&psb,  g_sb);
    cudaGetSymbolAddress((void**)&pknn, g_knn);

    const int SM_KNN = NN*16;                          // 65536
    const int SM0 = 128*88*2*2 + 2*64*4;               // 45568
    const int SM1 = 128*36*4*2 + (2*64 + 128)*4;       // 37888
    const int SM2 = 128*36*4*2 + (2*128 + 128)*4;      // 38400

    cudaFuncSetAttribute(knn_kernel, cudaFuncAttributeMaxDynamicSharedMemorySize, SM_KNN);
    cudaFuncSetAttribute(layer0_mma, cudaFuncAttributeMaxDynamicSharedMemorySize, SM0);
    cudaFuncSetAttribute(layer12_mma<64,false>,  cudaFuncAttributeMaxDynamicSharedMemorySize, SM1);
    cudaFuncSetAttribute(layer12_mma<128,true>, cudaFuncAttributeMaxDynamicSharedMemorySize, SM2);

    zero_stats_kernel<<<1, 512>>>(pst);
    knn_kernel<<<dim3(BB, 16), 256, SM_KNN>>>(xyz, fps, pknn, pnx, out);
    layer0_mma<<<ROWS/128, 256, SM0>>>(xyz, points, pknn, pnx, w0, b0, px0, pst, pst + 64);
    finalize_kernel<<<1, 64>>>(g0, be0, pst, psb, 64);
    layer12_mma<64,false><<<ROWS/128, 256, SM1>>>(px0, px1, w1, b1, psb, pst + 128, pst + 192, nullptr, nullptr);
    finalize_kernel<<<1, 64>>>(g1, be1, pst + 128, psb + 128, 64);
    layer12_mma<128,true><<<ROWS/128, 256, SM2>>>(px1, nullptr, w2, b2, psb + 128, pst + 256, pst + 384, pmx, pmn);
    finalize_kernel<<<1, 128>>>(g2, be2, pst + 256, psb + 256, 128);
    final_max_kernel<<<BB*SS*128/256, 256>>>(pmx, pmn, psb + 256, out);
}

// round 5
// speedup vs baseline: 3.3879x; 1.0006x over previous
#include <cuda_runtime.h>
#include <cuda_bf16.h>
#include <cstdint>

#define BB 16
#define NN 4096
#define SS 1024
#define KK 32
#define DD 64
#define ROWS (BB*SS*KK)        // 524288
#define XYZ_OUT (BB*SS*3)      // 49152
#define INV_ROWS (1.0f/524288.0f)

// ---------------- scratch ----------------
__device__ float g_x0[(size_t)ROWS*64];
__device__ float g_x1[(size_t)ROWS*64];
__device__ float g_maxv[(size_t)BB*SS*128];
__device__ float g_minv[(size_t)BB*SS*128];
__device__ int   g_knn[ROWS];
__device__ float g_newxyz[BB*SS*3];
__device__ float g_stats[512];
__device__ float g_sb[512];

__global__ void zero_stats_kernel(float* stats) {
    if (threadIdx.x < 512) stats[threadIdx.x] = 0.0f;
}

// ---------------- bf16 helpers ----------------
__device__ __forceinline__ void split2(float v0, float v1, uint32_t& hi, uint32_t& lo) {
    __nv_bfloat16 h0 = __float2bfloat16(v0), h1 = __float2bfloat16(v1);
    __nv_bfloat16 l0 = __float2bfloat16(v0 - __bfloat162float(h0));
    __nv_bfloat16 l1 = __float2bfloat16(v1 - __bfloat162float(h1));
    hi = (uint32_t)__bfloat16_as_ushort(h0) | ((uint32_t)__bfloat16_as_ushort(h1) << 16);
    lo = (uint32_t)__bfloat16_as_ushort(l0) | ((uint32_t)__bfloat16_as_ushort(l1) << 16);
}
__device__ __forceinline__ void mma_bf16(float& d0, float& d1, float& d2, float& d3,
    uint32_t a0, uint32_t a1, uint32_t a2, uint32_t a3, uint32_t b0, uint32_t b1)
{
    asm volatile("mma.sync.aligned.m16n8k16.row.col.f32.bf16.bf16.f32 "
        "{%0,%1,%2,%3},{%4,%5,%6,%7},{%8,%9},{%0,%1,%2,%3};"
        : "+f"(d0), "+f"(d1), "+f"(d2), "+f"(d3)
        : "r"(a0), "r"(a1), "r"(a2), "r"(a3), "r"(b0), "r"(b1));
}

// ---------------- KNN ----------------
// grid (16, 16), block 256 (8 warps, 8 queries/warp). smem caches batch xyz as float4 (x,y,z,|p|^2).
__global__ void knn_kernel(const float* __restrict__ xyz, const int* __restrict__ fps,
                           int* __restrict__ knn, float* __restrict__ newxyz,
                           float* __restrict__ out)
{
    extern __shared__ float4 sm4[];
    int b = blockIdx.x;
    const float* xb = xyz + (size_t)b*NN*3;
    for (int i = threadIdx.x; i < NN; i += blockDim.x) {
        float x = xb[3*i], y = xb[3*i+1], z = xb[3*i+2];
        sm4[i] = make_float4(x, y, z, x*x + y*y + z*z);
    }
    __syncthreads();
    int warp = threadIdx.x >> 5, lane = threadIdx.x & 31;

    for (int qi = 0; qi < 8; ++qi) {
        int s = blockIdx.y*64 + warp*8 + qi;
        int n0 = fps[b*SS + s];
        float4 q = sm4[n0];
        float qx = q.x, qy = q.y, qz = q.z, qq = q.w;

        float d; int myi;
        {
            float4 p = sm4[lane];
            d = fmaf(-2.0f, fmaf(qx, p.x, fmaf(qy, p.y, qz*p.z)), qq) + p.w;
            myi = lane;
        }
        float thr; int amax;
        {
            float v = d; int l = lane;
            #pragma unroll
            for (int off = 16; off; off >>= 1) {
                float ov = __shfl_down_sync(0xffffffffu, v, off);
                int   ol = __shfl_down_sync(0xffffffffu, l, off);
                if (ov > v) { v = ov; l = ol; }
            }
            thr  = __shfl_sync(0xffffffffu, v, 0);
            amax = __shfl_sync(0xffffffffu, l, 0);
        }

        for (int base = 32; base < NN; base += 32) {
            int i = base + lane;
            float4 p = sm4[i];
            float dc = fmaf(-2.0f, fmaf(qx, p.x, fmaf(qy, p.y, qz*p.z)), qq) + p.w;
            unsigned m = __ballot_sync(0xffffffffu, dc < thr);
            while (m) {
                int src = __ffs(m) - 1; m &= m - 1;
                float dcand = __shfl_sync(0xffffffffu, dc, src);
                if (dcand < thr) {
                    if (lane == amax) { d = dcand; myi = base + src; }
                    float v = d; int l = lane;
                    #pragma unroll
                    for (int off = 16; off; off >>= 1) {
                        float ov = __shfl_down_sync(0xffffffffu, v, off);
                        int   ol = __shfl_down_sync(0xffffffffu, l, off);
                        if (ov > v) { v = ov; l = ol; }
                    }
                    thr  = __shfl_sync(0xffffffffu, v, 0);
                    amax = __shfl_sync(0xffffffffu, l, 0);
                }
            }
        }
        knn[((size_t)b*SS + s)*KK + lane] = myi;
        if (lane == 0) {
            size_t o = ((size_t)b*SS + s)*3;
            newxyz[o] = qx; newxyz[o+1] = qy; newxyz[o+2] = qz;
            out[o] = qx; out[o+1] = qy; out[o+2] = qz;
        }
    }
}

// ---------------- shared MMA compute (bf16x3, m16n8k16) ----------------
// sHi/sLo: [128][STRIDE u32] activation tiles (packed bf16 pairs: hi, residual lo).
// Weights = A operand; D rows = out-channels, D cols = activation rows.
template<int COUT, int K_REAL, int NK, int STRIDE, bool MAXMIN>
__device__ __forceinline__ void mma_compute_bf16(
    const uint32_t* __restrict__ sHi, const uint32_t* __restrict__ sLo,
    const float* __restrict__ W, const float* __restrict__ bconv,
    float* __restrict__ xout, size_t rowBase, float* sS, float* sQ,
    float* __restrict__ gmax, float* __restrict__ gmin)
{
    constexpr int M_TILES = COUT/16;
    constexpr int HALVES  = 8/M_TILES;
    constexpr int ROWS_PW = 128/HALVES;
    constexpr int NG      = ROWS_PW/8;
    int warp = threadIdx.x >> 5, lane = threadIdx.x & 31;
    int g = lane >> 2, t = lane & 3;
    int mb = (warp % M_TILES) * 16;
    int rowOff = (warp / M_TILES) * ROWS_PW;

    uint32_t ahi[NK][4], alo[NK][4];
    #pragma unroll
    for (int ks = 0; ks < NK; ++ks) {
        #pragma unroll
        for (int j = 0; j < 4; ++j) {
            int r = mb + g + (j & 1) * 8;
            int c0 = ks*16 + 2*t + (j >> 1) * 8;
            float v0 = (c0     < K_REAL) ? W[r*K_REAL + c0]     : 0.0f;
            float v1 = (c0 + 1 < K_REAL) ? W[r*K_REAL + c0 + 1] : 0.0f;
            split2(v0, v1, ahi[ks][j], alo[ks][j]);
        }
    }
    float bias0 = bconv[mb + g], bias1 = bconv[mb + 8 + g];
    float s0 = 0, q0 = 0, s1 = 0, q1 = 0;
    float mx0 = -3.4e38f, mx1 = -3.4e38f, mn0 = 3.4e38f, mn1 = 3.4e38f;

    #pragma unroll 1
    for (int ng = 0; ng < NG; ++ng) {
        int nb = rowOff + ng*8;
        float d0 = bias0, d1 = bias0, d2 = bias1, d3 = bias1;
        const uint32_t* bh = sHi + (nb + g)*STRIDE + t;
        const uint32_t* bl = sLo + (nb + g)*STRIDE + t;
        #pragma unroll
        for (int ks = 0; ks < NK; ++ks) {
            uint32_t b0h = bh[ks*8];
            uint32_t b1h = bh[ks*8 + 4];
            uint32_t b0l = bl[ks*8];
            uint32_t b1l = bl[ks*8 + 4];
            mma_bf16(d0,d1,d2,d3, ahi[ks][0],ahi[ks][1],ahi[ks][2],ahi[ks][3], b0h,b1h);
            mma_bf16(d0,d1,d2,d3, ahi[ks][0],ahi[ks][1],ahi[ks][2],ahi[ks][3], b0l,b1l);
            mma_bf16(d0,d1,d2,d3, alo[ks][0],alo[ks][1],alo[ks][2],alo[ks][3], b0h,b1h);
        }
        if constexpr (!MAXMIN) {
            float* p = xout + (rowBase + nb + 2*t)*COUT + mb + g;
            p[0] = d0; p[COUT] = d1; p[8] = d2; p[COUT + 8] = d3;
        }
        s0 += d0 + d1; q0 += d0*d0 + d1*d1;
        s1 += d2 + d3; q1 += d2*d2 + d3*d3;
        if constexpr (MAXMIN) {
            mx0 = fmaxf(mx0, fmaxf(d0, d1)); mn0 = fminf(mn0, fminf(d0, d1));
            mx1 = fmaxf(mx1, fmaxf(d2, d3)); mn1 = fminf(mn1, fminf(d2, d3));
            if ((ng & 3) == 3) {
                #pragma unroll
                for (int off = 1; off < 4; off <<= 1) {
                    mx0 = fmaxf(mx0, __shfl_xor_sync(0xffffffffu, mx0, off));
                    mn0 = fminf(mn0, __shfl_xor_sync(0xffffffffu, mn0, off));
                    mx1 = fmaxf(mx1, __shfl_xor_sync(0xffffffffu, mx1, off));
                    mn1 = fminf(mn1, __shfl_xor_sync(0xffffffffu, mn1, off));
                }
                if (t == 0) {
                    int bs = (int)(rowBase >> 5) + (ng >> 2);
                    gmax[bs*128 + mb + g]     = mx0;  gmin[bs*128 + mb + g]     = mn0;
                    gmax[bs*128 + mb + 8 + g] = mx1;  gmin[bs*128 + mb + 8 + g] = mn1;
                }
                mx0 = mx1 = -3.4e38f; mn0 = mn1 = 3.4e38f;
            }
        }
    }
    #pragma unroll
    for (int off = 1; off < 4; off <<= 1) {
        s0 += __shfl_xor_sync(0xffffffffu, s0, off);
        q0 += __shfl_xor_sync(0xffffffffu, q0, off);
        s1 += __shfl_xor_sync(0xffffffffu, s1, off);
        q1 += __shfl_xor_sync(0xffffffffu, q1, off);
    }
    if (t == 0) {
        atomicAdd(&sS[mb + g], s0);     atomicAdd(&sQ[mb + g], q0);
        atomicAdd(&sS[mb + 8 + g], s1); atomicAdd(&sQ[mb + 8 + g], q1);
    }
}

// ---------------- Layer 0: gather + concat + 67->64 (padded 80) ----------------
// smem: sHi/sLo bf16 [128][88] (stride 44 u32), stats.
__global__ __launch_bounds__(256) void layer0_mma(
    const float* __restrict__ xyz, const float* __restrict__ points,
    const int* __restrict__ knn, const float* __restrict__ newxyz,
    const float* __restrict__ W, const float* __restrict__ bconv,
    float* __restrict__ xout, float* __restrict__ statS, float* __restrict__ statQ)
{
    extern __shared__ char smraw[];
    __nv_bfloat16* sHi = (__nv_bfloat16*)smraw;         // 128*88
    __nv_bfloat16* sLo = sHi + 128*88;
    float* sS = (float*)(sLo + 128*88);
    float* sQ = sS + 64;
    int tid = threadIdx.x;
    size_t rowBase = (size_t)blockIdx.x * 128;
    if (tid < 64) { sS[tid] = 0.0f; sQ[tid] = 0.0f; }

    {
        int r = tid >> 1, half = tid & 1;
        size_t row = rowBase + r;
        int b = (int)(row >> 15);
        int s = (int)((row >> 5) & 1023);
        int n = knn[row];
        const float4* prow = (const float4*)(points + ((size_t)b*NN + n)*DD);
        __nv_bfloat16* dh = sHi + r*88;
        __nv_bfloat16* dl = sLo + r*88;
        auto put = [&](int c, float v) {
            __nv_bfloat16 h = __float2bfloat16(v);
            dh[c] = h;
            dl[c] = __float2bfloat16(v - __bfloat162float(h));
        };
        if (half == 0) {
            size_t xo = ((size_t)b*NN + n)*3;
            size_t qo = ((size_t)b*SS + s)*3;
            put(0, xyz[xo]   - newxyz[qo]);
            put(1, xyz[xo+1] - newxyz[qo+1]);
            put(2, xyz[xo+2] - newxyz[qo+2]);
            #pragma unroll
            for (int j = 0; j < 8; ++j) {
                float4 v = prow[j];
                put(3+4*j, v.x); put(4+4*j, v.y); put(5+4*j, v.z); put(6+4*j, v.w);
            }
        } else {
            #pragma unroll
            for (int j = 8; j < 16; ++j) {
                float4 v = prow[j];
                put(3+4*j, v.x); put(4+4*j, v.y); put(5+4*j, v.z); put(6+4*j, v.w);
            }
            #pragma unroll
            for (int c = 67; c < 80; ++c) {
                dh[c] = __ushort_as_bfloat16(0); dl[c] = __ushort_as_bfloat16(0);
            }
        }
    }
    __syncthreads();
    mma_compute_bf16<64, 67, 5, 44, false>((const uint32_t*)sHi, (const uint32_t*)sLo,
        W, bconv, xout, rowBase, sS, sQ, nullptr, nullptr);
    __syncthreads();
    if (tid < 64) { atomicAdd(&statS[tid], sS[tid]); atomicAdd(&statQ[tid], sQ[tid]); }
}

// ---------------- Layers 1/2: BN+ReLU fused on load ----------------
template<int COUT, bool MAXMIN>
__global__ __launch_bounds__(256) void layer12_mma(
    const float* __restrict__ xin, float* __restrict__ xout,
    const float* __restrict__ W, const float* __restrict__ bconv,
    const float* __restrict__ sbin,
    float* __restrict__ statS, float* __restrict__ statQ,
    float* __restrict__ gmax, float* __restrict__ gmin)
{
    extern __shared__ char smraw[];
    uint32_t* sHi = (uint32_t*)smraw;       // 128*36
    uint32_t* sLo = sHi + 128*36;
    float* sS  = (float*)(sLo + 128*36);    // COUT
    float* sQ  = sS + COUT;
    float* sci = sQ + COUT;                 // 128
    int tid = threadIdx.x;
    size_t rowBase = (size_t)blockIdx.x * 128;

    if (tid < 128) sci[tid] = sbin[tid];
    for (int e = tid; e < COUT; e += 256) { sS[e] = 0.0f; sQ[e] = 0.0f; }
    __syncthreads();

    const float4* src = (const float4*)(xin + rowBase*64);
    #pragma unroll
    for (int k = 0; k < 8; ++k) {
        int e4 = tid + k*256;
        float4 v = src[e4];
        int lin = e4*4; int r = lin >> 6; int c = lin & 63;
        float y0 = fmaxf(fmaf(v.x, sci[c+0], sci[64+c+0]), 0.0f);
        float y1 = fmaxf(fmaf(v.y, sci[c+1], sci[64+c+1]), 0.0f);
        float y2 = fmaxf(fmaf(v.z, sci[c+2], sci[64+c+2]), 0.0f);
        float y3 = fmaxf(fmaf(v.w, sci[c+3], sci[64+c+3]), 0.0f);
        uint2 hv, lv;
        split2(y0, y1, hv.x, lv.x);
        split2(y2, y3, hv.y, lv.y);
        int off = r*36 + (c >> 1);
        *(uint2*)(sHi + off) = hv;
        *(uint2*)(sLo + off) = lv;
    }
    __syncthreads();
    mma_compute_bf16<COUT, 64, 4, 36, MAXMIN>(sHi, sLo, W, bconv, xout, rowBase,
        sS, sQ, gmax, gmin);
    __syncthreads();
    if (tid < COUT) { atomicAdd(&statS[tid], sS[tid]); atomicAdd(&statQ[tid], sQ[tid]); }
}

// ---------------- finalize BN params ----------------
__global__ void finalize_kernel(const float* __restrict__ gamma, const float* __restrict__ beta,
                                float* __restrict__ stats, float* __restrict__ sb, int cnt)
{
    int c = threadIdx.x;
    if (c < cnt) {
        float mean = stats[c] * INV_ROWS;
        float var  = stats[cnt + c] * INV_ROWS - mean*mean;
        float sc   = gamma[c] * rsqrtf(var + 1e-5f);
        sb[c]       = sc;
        sb[cnt + c] = beta[c] - mean*sc;
    }
}

// ---------------- final: BN+ReLU applied to max/min over K ----------------
__global__ void final_max_kernel(const float* __restrict__ gmax, const float* __restrict__ gmin,
                                 const float* __restrict__ sb, float* __restrict__ out)
{
    int i = blockIdx.x*256 + threadIdx.x;
    int ch = i & 127;
    float sc = sb[ch], bi = sb[128 + ch];
    float v = (sc >= 0.0f) ? gmax[i] : gmin[i];
    out[XYZ_OUT + i] = fmaxf(fmaf(v, sc, bi), 0.0f);
}

// ---------------- launch ----------------
extern "C" void kernel_launch(void* const* d_in, const int* in_sizes, int n_in,
                              void* d_out, int out_size)
{
    const float* xyz    = (const float*)d_in[0];
    const float* points = (const float*)d_in[1];
    const int*   fps    = (const int*)d_in[2];
    const float* w0  = (const float*)d_in[3];
    const float* b0  = (const float*)d_in[4];
    const float* g0  = (const float*)d_in[5];
    const float* be0 = (const float*)d_in[6];
    const float* w1  = (const float*)d_in[7];
    const float* b1  = (const float*)d_in[8];
    const float* g1  = (const float*)d_in[9];
    const float* be1 = (const float*)d_in[10];
    const float* w2  = (const float*)d_in[11];
    const float* b2  = (const float*)d_in[12];
    const float* g2  = (const float*)d_in[13];
    const float* be2 = (const float*)d_in[14];
    float* out = (float*)d_out;

    float *px0, *px1, *pmx, *pmn, *pnx, *pst, *psb;
    int* pknn;
    cudaGetSymbolAddress((void**)&px0,  g_x0);
    cudaGetSymbolAddress((void**)&px1,  g_x1);
    cudaGetSymbolAddress((void**)&pmx,  g_maxv);
    cudaGetSymbolAddress((void**)&pmn,  g_minv);
    cudaGetSymbolAddress((void**)&pnx,  g_newxyz);
    cudaGetSymbolAddress((void**)&pst,  g_stats);
    cudaGetSymbolAddress((void**)&psb,  g_sb);
    cudaGetSymbolAddress((void**)&pknn, g_knn);

    const int SM_KNN = NN*16;                          // 65536
    const int SM0 = 128*88*2*2 + 2*64*4;               // 45568
    const int SM1 = 128*36*4*2 + (2*64 + 128)*4;       // 37888
    const int SM2 = 128*36*4*2 + (2*128 + 128)*4;      // 38400

    cudaFuncSetAttribute(knn_kernel, cudaFuncAttributeMaxDynamicSharedMemorySize, SM_KNN);
    cudaFuncSetAttribute(layer0_mma, cudaFuncAttributeMaxDynamicSharedMemorySize, SM0);
    cudaFuncSetAttribute(layer12_mma<64,false>,  cudaFuncAttributeMaxDynamicSharedMemorySize, SM1);
    cudaFuncSetAttribute(layer12_mma<128,true>, cudaFuncAttributeMaxDynamicSharedMemorySize, SM2);

    zero_stats_kernel<<<1, 512>>>(pst);
    knn_kernel<<<dim3(BB, 16), 256, SM_KNN>>>(xyz, fps, pknn, pnx, out);
    layer0_mma<<<ROWS/128, 256, SM0>>>(xyz, points, pknn, pnx, w0, b0, px0, pst, pst + 64);
    finalize_kernel<<<1, 64>>>(g0, be0, pst, psb, 64);
    layer12_mma<64,false><<<ROWS/128, 256, SM1>>>(px0, px1, w1, b1, psb, pst + 128, pst + 192, nullptr, nullptr);
    finalize_kernel<<<1, 64>>>(g1, be1, pst + 128, psb + 128, 64);
    layer12_mma<128,true><<<ROWS/128, 256, SM2>>>(px1, nullptr, w2, b2, psb + 128, pst + 256, pst + 384, pmx, pmn);
    finalize_kernel<<<1, 128>>>(g2, be2, pst + 256, psb + 256, 128);
    final_max_kernel<<<BB*SS*128/256, 256>>>(pmx, pmn, psb + 256, out);
}

// round 6
// speedup vs baseline: 4.0521x; 1.1961x over previous
#include <cuda_runtime.h>
#include <cuda_bf16.h>
#include <cstdint>

#define BB 16
#define NN 4096
#define SS 1024
#define KK 32
#define DD 64
#define ROWS (BB*SS*KK)        // 524288
#define XYZ_OUT (BB*SS*3)      // 49152
#define INV_ROWS (1.0f/524288.0f)

// ---------------- scratch ----------------
__device__ float g_x0[(size_t)ROWS*64];
__device__ float g_x1[(size_t)ROWS*64];
__device__ float g_maxv[(size_t)BB*SS*128];
__device__ float g_minv[(size_t)BB*SS*128];
__device__ int   g_knn[ROWS];
__device__ float g_newxyz[BB*SS*3];
__device__ float g_stats[512];
__device__ float g_sb[512];
__device__ unsigned g_cnt[4];   // zero-init; each layer's last block resets its slot

// ---------------- bf16 helpers ----------------
__device__ __forceinline__ void split2(float v0, float v1, uint32_t& hi, uint32_t& lo) {
    __nv_bfloat16 h0 = __float2bfloat16(v0), h1 = __float2bfloat16(v1);
    __nv_bfloat16 l0 = __float2bfloat16(v0 - __bfloat162float(h0));
    __nv_bfloat16 l1 = __float2bfloat16(v1 - __bfloat162float(h1));
    hi = (uint32_t)__bfloat16_as_ushort(h0) | ((uint32_t)__bfloat16_as_ushort(h1) << 16);
    lo = (uint32_t)__bfloat16_as_ushort(l0) | ((uint32_t)__bfloat16_as_ushort(l1) << 16);
}
__device__ __forceinline__ void mma_bf16(float& d0, float& d1, float& d2, float& d3,
    uint32_t a0, uint32_t a1, uint32_t a2, uint32_t a3, uint32_t b0, uint32_t b1)
{
    asm volatile("mma.sync.aligned.m16n8k16.row.col.f32.bf16.bf16.f32 "
        "{%0,%1,%2,%3},{%4,%5,%6,%7},{%8,%9},{%0,%1,%2,%3};"
        : "+f"(d0), "+f"(d1), "+f"(d2), "+f"(d3)
        : "r"(a0), "r"(a1), "r"(a2), "r"(a3), "r"(b0), "r"(b1));
}

// ---------------- KNN: point-major, 8 register-resident query sets per warp ----------------
__global__ void knn_kernel(const float* __restrict__ xyz, const int* __restrict__ fps,
                           int* __restrict__ knn, float* __restrict__ newxyz,
                           float* __restrict__ out, float* __restrict__ stats)
{
    extern __shared__ float4 sm4[];
    if (blockIdx.x == 0 && blockIdx.y == 0) {
        for (int i = threadIdx.x; i < 512; i += blockDim.x) stats[i] = 0.0f;
    }
    int b = blockIdx.x;
    const float* xb = xyz + (size_t)b*NN*3;
    for (int i = threadIdx.x; i < NN; i += blockDim.x) {
        float x = xb[3*i], y = xb[3*i+1], z = xb[3*i+2];
        sm4[i] = make_float4(x, y, z, x*x + y*y + z*z);
    }
    __syncthreads();
    int warp = threadIdx.x >> 5, lane = threadIdx.x & 31;
    const unsigned F = 0xffffffffu;

    float qx[8], qy[8], qz[8], qq[8], dres[8], thr[8];
    int myi[8], amax[8];
    int sbase = blockIdx.y*64 + warp*8;

    #pragma unroll
    for (int q = 0; q < 8; ++q) {
        int n0 = fps[b*SS + sbase + q];
        float4 v = sm4[n0];
        qx[q] = v.x; qy[q] = v.y; qz[q] = v.z; qq[q] = v.w;
    }
    {
        float4 p = sm4[lane];
        #pragma unroll
        for (int q = 0; q < 8; ++q) {
            float dc = fmaxf(fmaf(-2.0f, fmaf(qx[q], p.x, fmaf(qy[q], p.y, qz[q]*p.z)), qq[q]) + p.w, 0.0f);
            dres[q] = dc; myi[q] = lane;
            int im = __reduce_max_sync(F, __float_as_int(dc));
            thr[q] = __int_as_float(im);
            amax[q] = __ffs(__ballot_sync(F, __float_as_int(dc) == im)) - 1;
        }
    }
    for (int base = 32; base < NN; base += 32) {
        float4 p = sm4[base + lane];
        #pragma unroll
        for (int q = 0; q < 8; ++q) {
            float dc = fmaxf(fmaf(-2.0f, fmaf(qx[q], p.x, fmaf(qy[q], p.y, qz[q]*p.z)), qq[q]) + p.w, 0.0f);
            unsigned m = __ballot_sync(F, dc < thr[q]);
            while (m) {
                int src = __ffs(m) - 1; m &= m - 1;
                float dcand = __shfl_sync(F, dc, src);
                if (dcand < thr[q]) {
                    if (lane == amax[q]) { dres[q] = dcand; myi[q] = base + src; }
                    int db = __float_as_int(dres[q]);
                    int im = __reduce_max_sync(F, db);
                    thr[q] = __int_as_float(im);
                    amax[q] = __ffs(__ballot_sync(F, db == im)) - 1;
                }
            }
        }
    }
    #pragma unroll
    for (int q = 0; q < 8; ++q) {
        int s = sbase + q;
        knn[((size_t)b*SS + s)*KK + lane] = myi[q];
        if (lane == 0) {
            size_t o = ((size_t)b*SS + s)*3;
            newxyz[o] = qx[q]; newxyz[o+1] = qy[q]; newxyz[o+2] = qz[q];
            out[o] = qx[q]; out[o+1] = qy[q]; out[o+2] = qz[q];
        }
    }
}

// ---------------- shared MMA compute (bf16x3, 3 independent accumulator chains) ----------------
template<int COUT, int K_REAL, int NK, int STRIDE, bool MAXMIN>
__device__ __forceinline__ void mma_compute_bf16(
    const uint32_t* __restrict__ sHi, const uint32_t* __restrict__ sLo,
    const float* __restrict__ W, const float* __restrict__ bconv,
    float* __restrict__ xout, size_t rowBase, float* sS, float* sQ,
    float* __restrict__ gmax, float* __restrict__ gmin)
{
    constexpr int M_TILES = COUT/16;
    constexpr int HALVES  = 8/M_TILES;
    constexpr int ROWS_PW = 128/HALVES;
    constexpr int NG      = ROWS_PW/8;
    int warp = threadIdx.x >> 5, lane = threadIdx.x & 31;
    int g = lane >> 2, t = lane & 3;
    int mb = (warp % M_TILES) * 16;
    int rowOff = (warp / M_TILES) * ROWS_PW;

    uint32_t ahi[NK][4], alo[NK][4];
    #pragma unroll
    for (int ks = 0; ks < NK; ++ks) {
        #pragma unroll
        for (int j = 0; j < 4; ++j) {
            int r = mb + g + (j & 1) * 8;
            int c0 = ks*16 + 2*t + (j >> 1) * 8;
            float v0 = (c0     < K_REAL) ? W[r*K_REAL + c0]     : 0.0f;
            float v1 = (c0 + 1 < K_REAL) ? W[r*K_REAL + c0 + 1] : 0.0f;
            split2(v0, v1, ahi[ks][j], alo[ks][j]);
        }
    }
    float bias0 = bconv[mb + g], bias1 = bconv[mb + 8 + g];
    float s0 = 0, q0 = 0, s1 = 0, q1 = 0;
    float mx0 = -3.4e38f, mx1 = -3.4e38f, mn0 = 3.4e38f, mn1 = 3.4e38f;

    #pragma unroll 1
    for (int ng = 0; ng < NG; ++ng) {
        int nb = rowOff + ng*8;
        float d0 = bias0, d1 = bias0, d2 = bias1, d3 = bias1;
        float e0 = 0, e1 = 0, e2 = 0, e3 = 0;
        float f0 = 0, f1 = 0, f2 = 0, f3 = 0;
        const uint32_t* bh = sHi + (nb + g)*STRIDE + t;
        const uint32_t* bl = sLo + (nb + g)*STRIDE + t;
        #pragma unroll
        for (int ks = 0; ks < NK; ++ks) {
            uint32_t b0h = bh[ks*8];
            uint32_t b1h = bh[ks*8 + 4];
            uint32_t b0l = bl[ks*8];
            uint32_t b1l = bl[ks*8 + 4];
            mma_bf16(d0,d1,d2,d3, ahi[ks][0],ahi[ks][1],ahi[ks][2],ahi[ks][3], b0h,b1h);
            mma_bf16(e0,e1,e2,e3, ahi[ks][0],ahi[ks][1],ahi[ks][2],ahi[ks][3], b0l,b1l);
            mma_bf16(f0,f1,f2,f3, alo[ks][0],alo[ks][1],alo[ks][2],alo[ks][3], b0h,b1h);
        }
        d0 += e0 + f0; d1 += e1 + f1; d2 += e2 + f2; d3 += e3 + f3;

        if constexpr (!MAXMIN) {
            float* p = xout + (rowBase + nb + 2*t)*COUT + mb + g;
            p[0] = d0; p[COUT] = d1; p[8] = d2; p[COUT + 8] = d3;
        }
        s0 += d0 + d1; q0 += d0*d0 + d1*d1;
        s1 += d2 + d3; q1 += d2*d2 + d3*d3;
        if constexpr (MAXMIN) {
            mx0 = fmaxf(mx0, fmaxf(d0, d1)); mn0 = fminf(mn0, fminf(d0, d1));
            mx1 = fmaxf(mx1, fmaxf(d2, d3)); mn1 = fminf(mn1, fminf(d2, d3));
            if ((ng & 3) == 3) {
                #pragma unroll
                for (int off = 1; off < 4; off <<= 1) {
                    mx0 = fmaxf(mx0, __shfl_xor_sync(0xffffffffu, mx0, off));
                    mn0 = fminf(mn0, __shfl_xor_sync(0xffffffffu, mn0, off));
                    mx1 = fmaxf(mx1, __shfl_xor_sync(0xffffffffu, mx1, off));
                    mn1 = fminf(mn1, __shfl_xor_sync(0xffffffffu, mn1, off));
                }
                if (t == 0) {
                    int bs = (int)(rowBase >> 5) + (ng >> 2);
                    gmax[bs*128 + mb + g]     = mx0;  gmin[bs*128 + mb + g]     = mn0;
                    gmax[bs*128 + mb + 8 + g] = mx1;  gmin[bs*128 + mb + 8 + g] = mn1;
                }
                mx0 = mx1 = -3.4e38f; mn0 = mn1 = 3.4e38f;
            }
        }
    }
    #pragma unroll
    for (int off = 1; off < 4; off <<= 1) {
        s0 += __shfl_xor_sync(0xffffffffu, s0, off);
        q0 += __shfl_xor_sync(0xffffffffu, q0, off);
        s1 += __shfl_xor_sync(0xffffffffu, s1, off);
        q1 += __shfl_xor_sync(0xffffffffu, q1, off);
    }
    if (t == 0) {
        atomicAdd(&sS[mb + g], s0);     atomicAdd(&sQ[mb + g], q0);
        atomicAdd(&sS[mb + 8 + g], s1); atomicAdd(&sQ[mb + 8 + g], q1);
    }
}

// ---------------- in-kernel BN finalize (last block) ----------------
template<int COUT>
__device__ __forceinline__ void tail_finalize(
    float* statS, float* statQ, const float* __restrict__ gamma,
    const float* __restrict__ beta, float* __restrict__ sb, unsigned* cnt)
{
    __shared__ bool isLast;
    int tid = threadIdx.x;
    __threadfence();
    if (tid == 0) isLast = (atomicAdd(cnt, 1u) == gridDim.x - 1);
    __syncthreads();
    if (isLast) {
        if (tid == 0) *cnt = 0;
        if (tid < COUT) {
            volatile float* vs = statS;
            volatile float* vq = statQ;
            float mean = vs[tid] * INV_ROWS;
            float var  = vq[tid] * INV_ROWS - mean*mean;
            float sc   = gamma[tid] * rsqrtf(var + 1e-5f);
            sb[tid]        = sc;
            sb[COUT + tid] = beta[tid] - mean*sc;
        }
    }
}

// ---------------- Layer 0: gather + concat + 67->64 ----------------
__global__ __launch_bounds__(256) void layer0_mma(
    const float* __restrict__ xyz, const float* __restrict__ points,
    const int* __restrict__ knn, const float* __restrict__ newxyz,
    const float* __restrict__ W, const float* __restrict__ bconv,
    float* __restrict__ xout, float* __restrict__ statS, float* __restrict__ statQ,
    const float* __restrict__ gamma, const float* __restrict__ beta,
    float* __restrict__ sb, unsigned* cnt)
{
    extern __shared__ char smraw[];
    __nv_bfloat16* sHi = (__nv_bfloat16*)smraw;         // 128*88
    __nv_bfloat16* sLo = sHi + 128*88;
    float* sS = (float*)(sLo + 128*88);
    float* sQ = sS + 64;
    int tid = threadIdx.x;
    size_t rowBase = (size_t)blockIdx.x * 128;
    if (tid < 64) { sS[tid] = 0.0f; sQ[tid] = 0.0f; }

    {
        int r = tid >> 1, half = tid & 1;
        size_t row = rowBase + r;
        int b = (int)(row >> 15);
        int s = (int)((row >> 5) & 1023);
        int n = knn[row];
        const float4* prow = (const float4*)(points + ((size_t)b*NN + n)*DD);
        __nv_bfloat16* dh = sHi + r*88;
        __nv_bfloat16* dl = sLo + r*88;
        auto put = [&](int c, float v) {
            __nv_bfloat16 h = __float2bfloat16(v);
            dh[c] = h;
            dl[c] = __float2bfloat16(v - __bfloat162float(h));
        };
        if (half == 0) {
            size_t xo = ((size_t)b*NN + n)*3;
            size_t qo = ((size_t)b*SS + s)*3;
            put(0, xyz[xo]   - newxyz[qo]);
            put(1, xyz[xo+1] - newxyz[qo+1]);
            put(2, xyz[xo+2] - newxyz[qo+2]);
            #pragma unroll
            for (int j = 0; j < 8; ++j) {
                float4 v = prow[j];
                put(3+4*j, v.x); put(4+4*j, v.y); put(5+4*j, v.z); put(6+4*j, v.w);
            }
        } else {
            #pragma unroll
            for (int j = 8; j < 16; ++j) {
                float4 v = prow[j];
                put(3+4*j, v.x); put(4+4*j, v.y); put(5+4*j, v.z); put(6+4*j, v.w);
            }
            #pragma unroll
            for (int c = 67; c < 80; ++c) {
                dh[c] = __ushort_as_bfloat16(0); dl[c] = __ushort_as_bfloat16(0);
            }
        }
    }
    __syncthreads();
    mma_compute_bf16<64, 67, 5, 44, false>((const uint32_t*)sHi, (const uint32_t*)sLo,
        W, bconv, xout, rowBase, sS, sQ, nullptr, nullptr);
    __syncthreads();
    if (tid < 64) { atomicAdd(&statS[tid], sS[tid]); atomicAdd(&statQ[tid], sQ[tid]); }
    tail_finalize<64>(statS, statQ, gamma, beta, sb, cnt);
}

// ---------------- Layers 1/2: BN+ReLU fused on load ----------------
template<int COUT, bool MAXMIN>
__global__ __launch_bounds__(256) void layer12_mma(
    const float* __restrict__ xin, float* __restrict__ xout,
    const float* __restrict__ W, const float* __restrict__ bconv,
    const float* __restrict__ sbin,
    float* __restrict__ statS, float* __restrict__ statQ,
    float* __restrict__ gmax, float* __restrict__ gmin,
    const float* __restrict__ gamma, const float* __restrict__ beta,
    float* __restrict__ sb, unsigned* cnt)
{
    extern __shared__ char smraw[];
    uint32_t* sHi = (uint32_t*)smraw;       // 128*36
    uint32_t* sLo = sHi + 128*36;
    float* sS  = (float*)(sLo + 128*36);    // COUT
    float* sQ  = sS + COUT;
    float* sci = sQ + COUT;                 // 128
    int tid = threadIdx.x;
    size_t rowBase = (size_t)blockIdx.x * 128;

    if (tid < 128) sci[tid] = sbin[tid];
    for (int e = tid; e < COUT; e += 256) { sS[e] = 0.0f; sQ[e] = 0.0f; }
    __syncthreads();

    const float4* src = (const float4*)(xin + rowBase*64);
    #pragma unroll
    for (int k = 0; k < 8; ++k) {
        int e4 = tid + k*256;
        float4 v = src[e4];
        int lin = e4*4; int r = lin >> 6; int c = lin & 63;
        float y0 = fmaxf(fmaf(v.x, sci[c+0], sci[64+c+0]), 0.0f);
        float y1 = fmaxf(fmaf(v.y, sci[c+1], sci[64+c+1]), 0.0f);
        float y2 = fmaxf(fmaf(v.z, sci[c+2], sci[64+c+2]), 0.0f);
        float y3 = fmaxf(fmaf(v.w, sci[c+3], sci[64+c+3]), 0.0f);
        uint2 hv, lv;
        split2(y0, y1, hv.x, lv.x);
        split2(y2, y3, hv.y, lv.y);
        int off = r*36 + (c >> 1);
        *(uint2*)(sHi + off) = hv;
        *(uint2*)(sLo + off) = lv;
    }
    __syncthreads();
    mma_compute_bf16<COUT, 64, 4, 36, MAXMIN>(sHi, sLo, W, bconv, xout, rowBase,
        sS, sQ, gmax, gmin);
    __syncthreads();
    if (tid < COUT) { atomicAdd(&statS[tid], sS[tid]); atomicAdd(&statQ[tid], sQ[tid]); }
    tail_finalize<COUT>(statS, statQ, gamma, beta, sb, cnt);
}

// ---------------- final: BN+ReLU applied to max/min over K ----------------
__global__ void final_max_kernel(const float* __restrict__ gmax, const float* __restrict__ gmin,
                                 const float* __restrict__ sb, float* __restrict__ out)
{
    int i = blockIdx.x*256 + threadIdx.x;
    int ch = i & 127;
    float sc = sb[ch], bi = sb[128 + ch];
    float v = (sc >= 0.0f) ? gmax[i] : gmin[i];
    out[XYZ_OUT + i] = fmaxf(fmaf(v, sc, bi), 0.0f);
}

// ---------------- launch ----------------
extern "C" void kernel_launch(void* const* d_in, const int* in_sizes, int n_in,
                              void* d_out, int out_size)
{
    const float* xyz    = (const float*)d_in[0];
    const float* points = (const float*)d_in[1];
    const int*   fps    = (const int*)d_in[2];
    const float* w0  = (const float*)d_in[3];
    const float* b0  = (const float*)d_in[4];
    const float* g0  = (const float*)d_in[5];
    const float* be0 = (const float*)d_in[6];
    const float* w1  = (const float*)d_in[7];
    const float* b1  = (const float*)d_in[8];
    const float* g1  = (const float*)d_in[9];
    const float* be1 = (const float*)d_in[10];
    const float* w2  = (const float*)d_in[11];
    const float* b2  = (const float*)d_in[12];
    const float* g2  = (const float*)d_in[13];
    const float* be2 = (const float*)d_in[14];
    float* out = (float*)d_out;

    float *px0, *px1, *pmx, *pmn, *pnx, *pst, *psb;
    int* pknn;
    unsigned* pcnt;
    cudaGetSymbolAddress((void**)&px0,  g_x0);
    cudaGetSymbolAddress((void**)&px1,  g_x1);
    cudaGetSymbolAddress((void**)&pmx,  g_maxv);
    cudaGetSymbolAddress((void**)&pmn,  g_minv);
    cudaGetSymbolAddress((void**)&pnx,  g_newxyz);
    cudaGetSymbolAddress((void**)&pst,  g_stats);
    cudaGetSymbolAddress((void**)&psb,  g_sb);
    cudaGetSymbolAddress((void**)&pknn, g_knn);
    cudaGetSymbolAddress((void**)&pcnt, g_cnt);

    const int SM_KNN = NN*16;                          // 65536
    const int SM0 = 128*88*2*2 + 2*64*4;               // 45568
    const int SM1 = 128*36*4*2 + (2*64 + 128)*4;       // 37888
    const int SM2 = 128*36*4*2 + (2*128 + 128)*4;      // 38400

    cudaFuncSetAttribute(knn_kernel, cudaFuncAttributeMaxDynamicSharedMemorySize, SM_KNN);
    cudaFuncSetAttribute(layer0_mma, cudaFuncAttributeMaxDynamicSharedMemorySize, SM0);
    cudaFuncSetAttribute(layer12_mma<64,false>,  cudaFuncAttributeMaxDynamicSharedMemorySize, SM1);
    cudaFuncSetAttribute(layer12_mma<128,true>, cudaFuncAttributeMaxDynamicSharedMemorySize, SM2);

    knn_kernel<<<dim3(BB, 16), 256, SM_KNN>>>(xyz, fps, pknn, pnx, out, pst);
    layer0_mma<<<ROWS/128, 256, SM0>>>(xyz, points, pknn, pnx, w0, b0, px0,
        pst, pst + 64, g0, be0, psb, pcnt);
    layer12_mma<64,false><<<ROWS/128, 256, SM1>>>(px0, px1, w1, b1, psb,
        pst + 128, pst + 192, nullptr, nullptr, g1, be1, psb + 128, pcnt + 1);
    layer12_mma<128,true><<<ROWS/128, 256, SM2>>>(px1, nullptr, w2, b2, psb + 128,
        pst + 256, pst + 384, pmx, pmn, g2, be2, psb + 256, pcnt + 2);
    final_max_kernel<<<BB*SS*128/256, 256>>>(pmx, pmn, psb + 256, out);
}